// round 5
// baseline (speedup 1.0000x reference)
#include <cuda_runtime.h>
#include <cuda_fp16.h>
#include <cstdint>

// Inputs (metadata order):
// 0: x [N,64] f32   1: node_batch [N] int32-or-int64 (sorted)  2: global_attr [B,3] f32
// 3: Wg [3,64] f32  4: bg [64] f32  5: Wn [128,64] f32  6: bn [64] f32
// 7: Wa [64,1] f32  8: ba [1] f32
// out: w [N,1] f32   (holds score s between k_main and k_soft)

#define BMAX 8192
#define BMSK (BMAX - 1)

__device__ float d_c[BMAX * 64];   // c[b] = (ga_b@Wg+bg) @ Wn[64:] + bn
__device__ int   d_start[BMAX];
__device__ int   d_end[BMAX];
__device__ int   d_is64;

// ---------------- helpers ----------------

__device__ __forceinline__ uint32_t s2u(const void* p) {
    return (uint32_t)__cvta_generic_to_shared(p);
}

__device__ __forceinline__ void ldm_x4(uint32_t* r, uint32_t addr) {
    asm volatile("ldmatrix.sync.aligned.m8n8.x4.shared.b16 {%0,%1,%2,%3}, [%4];"
                 : "=r"(r[0]), "=r"(r[1]), "=r"(r[2]), "=r"(r[3]) : "r"(addr));
}
__device__ __forceinline__ void ldm_x4t(uint32_t* r, uint32_t addr) {
    asm volatile("ldmatrix.sync.aligned.m8n8.x4.trans.shared.b16 {%0,%1,%2,%3}, [%4];"
                 : "=r"(r[0]), "=r"(r[1]), "=r"(r[2]), "=r"(r[3]) : "r"(addr));
}
__device__ __forceinline__ void mma16816(float* d, const uint32_t* a, const uint32_t* b) {
    asm volatile("mma.sync.aligned.m16n8k16.row.col.f32.f16.f16.f32 "
                 "{%0,%1,%2,%3}, {%4,%5,%6,%7}, {%8,%9}, {%0,%1,%2,%3};"
                 : "+f"(d[0]), "+f"(d[1]), "+f"(d[2]), "+f"(d[3])
                 : "r"(a[0]), "r"(a[1]), "r"(a[2]), "r"(a[3]), "r"(b[0]), "r"(b[1]));
}

// segment id read, dtype-branched; always in-bounds under either dtype
__device__ __forceinline__ int seg_at(const void* nbraw, int i) {
    if (d_is64) return ((int)((const long long*)nbraw)[i]) & BMSK;
    return ((const int*)nbraw)[i] & BMSK;
}

// stable softplus via EX2/LG2
__device__ __forceinline__ float softplusf(float z) {
    float az = fabsf(z);
    float t = az * -1.4426950408889634f;
    float p, l;
    asm("ex2.approx.ftz.f32 %0, %1;" : "=f"(p) : "f"(t));
    float op = 1.0f + p;
    asm("lg2.approx.ftz.f32 %0, %1;" : "=f"(l) : "f"(op));
    return fmaxf(z, 0.0f) + 0.6931471805599453f * l;
}

__device__ __forceinline__ float exp2a(float t) {
    float e;
    asm("ex2.approx.ftz.f32 %0, %1;" : "=f"(e) : "f"(t));
    return e;
}

// ---------------- kernel 0: detect node_batch dtype ----------------
__global__ void k_detect(const int* __restrict__ p32, int n) {
    int last = n - 1;
    if (!(last & 1)) last--;
    int acc = 0;
    for (int k = 0; k < 8; k++) {
        int idx = last - 2 * k;
        if (idx >= 1) acc |= p32[idx];
    }
    d_is64 = (acc == 0) ? 1 : 0;
}

// ---------------- kernel 1: per-graph c[b] + init start/end ----------------

__global__ void k_graph(const float* __restrict__ ga, const float* __restrict__ Wg,
                        const float* __restrict__ bg, const float* __restrict__ Wn,
                        const float* __restrict__ bn) {
    int b = blockIdx.x;
    int j = threadIdx.x; // 0..63
    __shared__ float g[64];
    float a0 = ga[b * 3 + 0], a1 = ga[b * 3 + 1], a2 = ga[b * 3 + 2];
    g[j] = bg[j] + a0 * Wg[j] + a1 * Wg[64 + j] + a2 * Wg[128 + j];
    if (j == 0) {
        d_start[b] = 0x7FFFFFFF;
        d_end[b] = 0;
    }
    __syncthreads();
    float acc = bn[j];
#pragma unroll
    for (int i = 0; i < 64; i++)
        acc = fmaf(g[i], Wn[(64 + i) * 64 + j], acc);
    d_c[b * 64 + j] = acc;
}

// ---------------- kernel 1b: segment boundaries ----------------

__global__ void k_bound(const void* __restrict__ nbraw, int n) {
    int i = blockIdx.x * blockDim.x + threadIdx.x;
    if (i >= n) return;
    int v = seg_at(nbraw, i);
    int pv = (i > 0) ? seg_at(nbraw, i - 1) : -1;
    int nx = (i + 1 < n) ? seg_at(nbraw, i + 1) : -2;
    if (v != pv) atomicMin(&d_start[v], i);
    if (v != nx) atomicMax(&d_end[v], i + 1);
}

// ---------------- kernel 2: fused GEMM + softplus + dot -> s ----------------

#define LDA 72
#define LDB 72

__global__ void __launch_bounds__(256)
k_main(const float* __restrict__ x, const void* __restrict__ nbraw,
       const float* __restrict__ Wn, const float* __restrict__ Wa,
       const float* __restrict__ ba, float* __restrict__ out, int n) {
    __shared__ __align__(16) __half smA[128 * LDA];
    __shared__ __align__(16) __half smB[64 * LDB];
    __shared__ float sWa[64];
    __shared__ float sba;

    const int tid = threadIdx.x;
    const int wid = tid >> 5;
    const int lane = tid & 31;
    const int wbase = wid * 16;     // 8 warps x 16 rows
    const int r0 = blockIdx.x * 128;

    if (tid == 0) sba = ba[0];
    if (tid < 64) sWa[tid] = Wa[tid];

    // B = Wn[0:64,:] row-major (k x n), f32 -> f16
#pragma unroll
    for (int it = 0; it < 8; it++) {
        int idx = it * 512 + tid * 2;
        int k = idx >> 6;
        int nn = idx & 63;
        float2 w = *reinterpret_cast<const float2*>(Wn + k * 64 + nn);
        __half2 h = __floats2half2_rn(w.x, w.y);
        *reinterpret_cast<__half2*>(smB + k * LDB + nn) = h;
    }

    // A = x tile [128,64] f32 -> f16 (zero-pad tail rows)
#pragma unroll
    for (int it = 0; it < 8; it++) {
        int f4 = it * 256 + tid;
        int row = f4 >> 4;
        int c4 = (f4 & 15) * 4;
        int g = r0 + row;
        float4 v = make_float4(0.f, 0.f, 0.f, 0.f);
        if (g < n) v = *reinterpret_cast<const float4*>(x + (long long)g * 64 + c4);
        __half2 h0 = __floats2half2_rn(v.x, v.y);
        __half2 h1 = __floats2half2_rn(v.z, v.w);
        uint2 pv;
        pv.x = *reinterpret_cast<uint32_t*>(&h0);
        pv.y = *reinterpret_cast<uint32_t*>(&h1);
        *reinterpret_cast<uint2*>(smA + row * LDA + c4) = pv;
    }
    __syncthreads();

    const uint32_t aA = s2u(smA), aB = s2u(smB);

    // Warp computes rows [wbase, wbase+16) x cols [0,64), K=64
    float d[8][4];
#pragma unroll
    for (int nt = 0; nt < 8; nt++)
#pragma unroll
        for (int q = 0; q < 4; q++) d[nt][q] = 0.f;

#pragma unroll
    for (int kk = 0; kk < 4; kk++) {
        uint32_t a[4];
        {
            uint32_t addr = aA + ((wbase + (lane & 15)) * LDA +
                                  kk * 16 + ((lane >> 4) << 3)) * 2;
            ldm_x4(a, addr);
        }
        uint32_t b[16];
#pragma unroll
        for (int np = 0; np < 4; np++) {
            uint32_t addr = aB + ((kk * 16 + (lane & 15)) * LDB +
                                  np * 16 + ((lane >> 4) << 3)) * 2;
            ldm_x4t(b + np * 4, addr);
        }
#pragma unroll
        for (int nt = 0; nt < 8; nt++)
            mma16816(d[nt], a, b + nt * 2);
    }

    // Epilogue: thread holds rows {wbase+g8, wbase+g8+8}, cols {8nt+2l3, 8nt+2l3+1}
    const int g8 = lane >> 2;
    const int l3 = lane & 3;

    float2 wv[8];
#pragma unroll
    for (int nt = 0; nt < 8; nt++)
        wv[nt] = *reinterpret_cast<const float2*>(sWa + nt * 8 + 2 * l3);

#pragma unroll
    for (int h = 0; h < 2; h++) {
        int gr = r0 + wbase + h * 8 + g8;
        int sg = (gr < n) ? seg_at(nbraw, gr) : 0;
        const float2* cp = reinterpret_cast<const float2*>(d_c + sg * 64);
        float acc = 0.f;
#pragma unroll
        for (int nt = 0; nt < 8; nt++) {
            float2 cc = __ldg(cp + nt * 4 + l3);
            float v0 = d[nt][h * 2 + 0] + cc.x;
            float v1 = d[nt][h * 2 + 1] + cc.y;
            acc = fmaf(wv[nt].x, softplusf(v0), acc);
            acc = fmaf(wv[nt].y, softplusf(v1), acc);
        }
        acc += __shfl_xor_sync(0xFFFFFFFFu, acc, 1);
        acc += __shfl_xor_sync(0xFFFFFFFFu, acc, 2);
        if (l3 == 0 && gr < n) out[gr] = acc + sba;
    }
}

// ---------------- kernel 3: per-graph softmax (max, exp, sum, normalize) ----------------

#define CH 6   // register-cached elements per thread (covers count <= 1536)

__global__ void __launch_bounds__(256)
k_soft(float* __restrict__ out, int n) {
    const int b = blockIdx.x;
    int start = d_start[b];
    int end = d_end[b];
    if (end > n) end = n;
    if (start >= end) return;

    const int tid = threadIdx.x;
    const int lane = tid & 31;
    const int wid = tid >> 5;
    __shared__ float red[8];
    __shared__ float sm, sden;

    const int base = start + tid;
    float vals[CH];
    float lm = __int_as_float(0xFF800000);
#pragma unroll
    for (int c = 0; c < CH; c++) {
        int i = base + c * 256;
        if (i < end) { vals[c] = out[i]; lm = fmaxf(lm, vals[c]); }
    }
    for (int i = base + CH * 256; i < end; i += 256)
        lm = fmaxf(lm, out[i]);

#pragma unroll
    for (int off = 16; off; off >>= 1)
        lm = fmaxf(lm, __shfl_xor_sync(0xFFFFFFFFu, lm, off));
    if (lane == 0) red[wid] = lm;
    __syncthreads();
    if (tid == 0) {
        float m = red[0];
#pragma unroll
        for (int k = 1; k < 8; k++) m = fmaxf(m, red[k]);
        sm = m;
    }
    __syncthreads();
    const float m = sm;

    float ls = 0.f;
#pragma unroll
    for (int c = 0; c < CH; c++) {
        int i = base + c * 256;
        if (i < end) {
            float e = exp2a((vals[c] - m) * 1.4426950408889634f);
            vals[c] = e;
            ls += e;
        }
    }
    for (int i = base + CH * 256; i < end; i += 256)
        ls += exp2a((out[i] - m) * 1.4426950408889634f);

#pragma unroll
    for (int off = 16; off; off >>= 1)
        ls += __shfl_xor_sync(0xFFFFFFFFu, ls, off);
    if (lane == 0) red[wid] = ls;
    __syncthreads();
    if (tid == 0) {
        float s = 0.f;
#pragma unroll
        for (int k = 1; k < 8; k++) s += red[k];
        sden = s + red[0] + 1e-16f;
    }
    __syncthreads();
    const float inv = 1.0f / sden;

#pragma unroll
    for (int c = 0; c < CH; c++) {
        int i = base + c * 256;
        if (i < end) out[i] = vals[c] * inv;
    }
    for (int i = base + CH * 256; i < end; i += 256)
        out[i] = exp2a((out[i] - m) * 1.4426950408889634f) * inv;
}

// ---------------- launch ----------------

extern "C" void kernel_launch(void* const* d_in, const int* in_sizes, int n_in,
                              void* d_out, int out_size) {
    const float* x = (const float*)d_in[0];
    const void* nb = d_in[1];
    const float* ga = (const float*)d_in[2];
    const float* Wg = (const float*)d_in[3];
    const float* bg = (const float*)d_in[4];
    const float* Wn = (const float*)d_in[5];
    const float* bn = (const float*)d_in[6];
    const float* Wa = (const float*)d_in[7];
    const float* ba = (const float*)d_in[8];
    float* out = (float*)d_out;

    int n = in_sizes[0] / 64;
    if (n > out_size) n = out_size;
    int B = in_sizes[2] / 3;
    if (B > BMAX) B = BMAX;

    int blk = (n + 255) / 256;

    k_detect<<<1, 1>>>((const int*)nb, n);
    k_graph<<<B, 64>>>(ga, Wg, bg, Wn, bn);
    k_bound<<<blk, 256>>>(nb, n);

    int tiles = (n + 127) / 128;
    k_main<<<tiles, 256>>>(x, nb, Wn, Wa, ba, out, n);

    k_soft<<<B, 256>>>(out, n);
}